// round 10
// baseline (speedup 1.0000x reference)
#include <cuda_runtime.h>
#include <cuda_bf16.h>
#include <cmath>
#include <cstdint>

// Problem constants (fixed by setup_inputs: B=8, L=20*50+1, d_model=1024, H=16, 2 layers)
namespace {
constexpr int B    = 8;
constexpr int L    = 1001;
constexpr int D    = 1024;
constexpr int H    = 16;
constexpr int DK   = 64;
constexpr int NKQ  = 1000;   // query row index
constexpr int KCLS = 50;     // class block size
constexpr int TI   = 64;     // row tile (4 warps x 16)
constexpr int TJ   = 64;     // key tile
constexpr int NT   = (L + TJ - 1) / TJ;   // 16
constexpr int LDS  = 72;     // bf16 elems per smem row (144B stride: conflict-free ldmatrix)
constexpr int TILE = TJ * LDS;            // elems per hi (or lo) tile
constexpr int BUFE = 2 * TILE;            // elems per buffer (hi+lo)
constexpr int SMEM_BYTES = 4 * BUFE * 2;  // 4 buffers = 73728 B
// fixed-base softmax: e^(s/8 - 24) = 2^(acc*C1 + C0). Scores are bounded (|s|<~16,
// diag >= 0 so denominator never vanishes); the common e^-24 scale cancels in o/l.
constexpr float C1 = 0.125f * 1.4426950408889634f;
constexpr float C0 = -24.0f * 1.4426950408889634f;
}

// bf16 hi/lo split activations (global scratch; no-alloc rule).
__device__ __nv_bfloat16 g_xh[(size_t)B * L * D];
__device__ __nv_bfloat16 g_xl[(size_t)B * L * D];
__device__ __nv_bfloat16 g_yh[(size_t)B * L * D];
__device__ __nv_bfloat16 g_yl[(size_t)B * L * D];

__device__ __forceinline__ uint32_t smem_u32(const void* p) {
    return (uint32_t)__cvta_generic_to_shared(p);
}
__device__ __forceinline__ void ldmx4(uint32_t a, uint32_t& r0, uint32_t& r1, uint32_t& r2, uint32_t& r3) {
    asm volatile("ldmatrix.sync.aligned.m8n8.x4.shared.b16 {%0,%1,%2,%3},[%4];"
                 : "=r"(r0), "=r"(r1), "=r"(r2), "=r"(r3) : "r"(a));
}
__device__ __forceinline__ void ldmx4t(uint32_t a, uint32_t& r0, uint32_t& r1, uint32_t& r2, uint32_t& r3) {
    asm volatile("ldmatrix.sync.aligned.m8n8.x4.trans.shared.b16 {%0,%1,%2,%3},[%4];"
                 : "=r"(r0), "=r"(r1), "=r"(r2), "=r"(r3) : "r"(a));
}
__device__ __forceinline__ void mma_bf16(float* d, const uint32_t* a, uint32_t b0, uint32_t b1) {
    asm volatile("mma.sync.aligned.m16n8k16.row.col.f32.bf16.bf16.f32 "
                 "{%0,%1,%2,%3},{%4,%5,%6,%7},{%8,%9},{%0,%1,%2,%3};"
                 : "+f"(d[0]), "+f"(d[1]), "+f"(d[2]), "+f"(d[3])
                 : "r"(a[0]), "r"(a[1]), "r"(a[2]), "r"(a[3]), "r"(b0), "r"(b1));
}
__device__ __forceinline__ float ex2(float x) {
    float r; asm("ex2.approx.ftz.f32 %0,%1;" : "=f"(r) : "f"(x)); return r;
}
// Fast 2-term bf16 split of pair (a,b): a -> low halves, b -> high halves.
__device__ __forceinline__ void split2(float a, float b, uint32_t& hi, uint32_t& lo) {
    uint32_t h;
    asm("cvt.rn.bf16x2.f32 %0, %1, %2;" : "=r"(h) : "f"(b), "f"(a));
    const float fa = __uint_as_float(h << 16);
    const float fb = __uint_as_float(h & 0xffff0000u);
    uint32_t l;
    asm("cvt.rn.bf16x2.f32 %0, %1, %2;" : "=r"(l) : "f"(b - fb), "f"(a - fa));
    hi = h; lo = l;
}
__device__ __forceinline__ void cp_commit() { asm volatile("cp.async.commit_group;"); }
template<int N> __device__ __forceinline__ void cp_wait() {
    asm volatile("cp.async.wait_group %0;" :: "n"(N));
}

// Async-stage a 64-row tile (this head's 64 bf16 cols) of hi+lo into smem buffer.
// 1024 16B chunks / 128 threads = 8 per thread. OOB rows zero-filled via src-size=0.
__device__ __forceinline__ void stage_async(const __nv_bfloat16* __restrict__ gh,
                                            const __nv_bfloat16* __restrict__ gl,
                                            int base_row, __nv_bfloat16* sbuf, int tid) {
#pragma unroll
    for (int it = 0; it < 8; ++it) {
        int idx = tid + 128 * it;          // 0..1023
        int arr = idx >> 9;                // 0 = hi, 1 = lo
        int rem = idx & 511;
        int row = rem >> 3;
        int ch  = rem & 7;                 // 16B chunk within 128B row segment
        int g   = base_row + row;
        const __nv_bfloat16* src = (arr ? gl : gh) + (size_t)g * D + ch * 8;
        uint32_t dst = smem_u32(sbuf + arr * TILE + row * LDS + ch * 8);
        int sz = (g < L) ? 16 : 0;
        asm volatile("cp.async.ca.shared.global [%0], [%1], 16, %2;"
                     :: "r"(dst), "l"(src), "r"(sz));
    }
}

// ---- S = Q K^T (bf16x3, unscaled): zero acc then 96 MMAs from K buffer ----
__device__ __forceinline__ void s_phase(const __nv_bfloat16* kb,
                                        const uint32_t (&qh)[4][4], const uint32_t (&ql)[4][4],
                                        float (&acc)[8][4], int lrK, int lcK) {
#pragma unroll
    for (int nt = 0; nt < 8; ++nt)
#pragma unroll
        for (int v = 0; v < 4; ++v) acc[nt][v] = 0.f;
#pragma unroll
    for (int kc = 0; kc < 4; ++kc) {
#pragma unroll
        for (int ntp = 0; ntp < 4; ++ntp) {
            const int off = (16 * ntp + lrK) * LDS + kc * 16 + lcK;
            uint32_t bh0, bh1, bh2, bh3, bl0, bl1, bl2, bl3;
            ldmx4(smem_u32(kb + off),        bh0, bh1, bh2, bh3);
            ldmx4(smem_u32(kb + TILE + off), bl0, bl1, bl2, bl3);
            mma_bf16(acc[2 * ntp],     qh[kc], bh0, bh1);
            mma_bf16(acc[2 * ntp],     qh[kc], bl0, bl1);
            mma_bf16(acc[2 * ntp],     ql[kc], bh0, bh1);
            mma_bf16(acc[2 * ntp + 1], qh[kc], bh2, bh3);
            mma_bf16(acc[2 * ntp + 1], qh[kc], bl2, bl3);
            mma_bf16(acc[2 * ntp + 1], ql[kc], bh2, bh3);
        }
    }
}

// ---- O += P V (V tile == K tile data, trans ldmatrix) ----
__device__ __forceinline__ void pv_phase(const __nv_bfloat16* kb,
                                         const uint32_t (&ah)[4][4], const uint32_t (&al)[4][4],
                                         float (&o)[8][4], int lrA, int lcA) {
#pragma unroll
    for (int kc = 0; kc < 4; ++kc) {
#pragma unroll
        for (int ntp = 0; ntp < 4; ++ntp) {
            const int off = (kc * 16 + lrA) * LDS + 16 * ntp + lcA;
            uint32_t vh0, vh1, vh2, vh3, vl0, vl1, vl2, vl3;
            ldmx4t(smem_u32(kb + off),        vh0, vh1, vh2, vh3);
            ldmx4t(smem_u32(kb + TILE + off), vl0, vl1, vl2, vl3);
            mma_bf16(o[2 * ntp],     ah[kc], vh0, vh1);
            mma_bf16(o[2 * ntp],     ah[kc], vl0, vl1);
            mma_bf16(o[2 * ntp],     al[kc], vh0, vh1);
            mma_bf16(o[2 * ntp + 1], ah[kc], vh2, vh3);
            mma_bf16(o[2 * ntp + 1], ah[kc], vl2, vl3);
            mma_bf16(o[2 * ntp + 1], al[kc], vh2, vh3);
        }
    }
}

// Softmax + structured multiplier + pack P into A-fragments.
// wr* = {w_in_class, w_out_class, w_diag, w_querycol} per owned row.
template<bool MASK>
__device__ __forceinline__ void softmax_pack(const float (&acc)[8][4], int j_base,
                                             int gi0, int gi1, int jlo0, int jlo1,
                                             const float* wr0, const float* wr1,
                                             uint32_t (&ah)[4][4], uint32_t (&al)[4][4],
                                             float& l0, float& l1, int lane)
{
#pragma unroll
    for (int nt = 0; nt < 8; ++nt) {
        const int gj0 = j_base + nt * 8 + (lane & 3) * 2;
        const int gj1 = gj0 + 1;
        float e00 = ex2(fmaf(acc[nt][0], C1, C0));
        float e01 = ex2(fmaf(acc[nt][1], C1, C0));
        float e10 = ex2(fmaf(acc[nt][2], C1, C0));
        float e11 = ex2(fmaf(acc[nt][3], C1, C0));
        if (MASK) {
            if (gj0 >= L) { e00 = 0.f; e10 = 0.f; }
            if (gj1 >= L) { e01 = 0.f; e11 = 0.f; }
        }
        l0 += e00 + e01;
        l1 += e10 + e11;
        float t00 = ((unsigned)(gj0 - jlo0) < (unsigned)KCLS) ? wr0[0] : wr0[1];
        float t01 = ((unsigned)(gj1 - jlo0) < (unsigned)KCLS) ? wr0[0] : wr0[1];
        float t10 = ((unsigned)(gj0 - jlo1) < (unsigned)KCLS) ? wr1[0] : wr1[1];
        float t11 = ((unsigned)(gj1 - jlo1) < (unsigned)KCLS) ? wr1[0] : wr1[1];
        if (gj0 == gi0) t00 = wr0[2];
        if (gj1 == gi0) t01 = wr0[2];
        if (gj0 == gi1) t10 = wr1[2];
        if (gj1 == gi1) t11 = wr1[2];
        if (gj0 == NKQ) { t00 = wr0[3]; t10 = wr1[3]; }
        if (gj1 == NKQ) { t01 = wr0[3]; t11 = wr1[3]; }
        const int kc = nt >> 1, of = (nt & 1) * 2;
        split2(e00 * t00, e01 * t01, ah[kc][of],     al[kc][of]);
        split2(e10 * t10, e11 * t11, ah[kc][of + 1], al[kc][of + 1]);
    }
}

// Initial fp32 -> bf16 hi/lo split (one-time).
__global__ void convert_split(const float* __restrict__ x,
                              __nv_bfloat16* __restrict__ xh,
                              __nv_bfloat16* __restrict__ xl) {
    size_t i = ((size_t)blockIdx.x * blockDim.x + threadIdx.x) * 4;
    float4 v = *reinterpret_cast<const float4*>(x + i);
    uint32_t h0, l0, h1, l1;
    split2(v.x, v.y, h0, l0);
    split2(v.z, v.w, h1, l1);
    *reinterpret_cast<uint2*>(xh + i) = make_uint2(h0, h1);
    *reinterpret_cast<uint2*>(xl + i) = make_uint2(l0, l1);
}

template<bool SPLIT_OUT>
__global__ void __launch_bounds__(128, 3)
encoder_layer_tc(const __nv_bfloat16* __restrict__ xh,
                 const __nv_bfloat16* __restrict__ xl,
                 const float* __restrict__ w6,        // [H][6] for this layer
                 __nv_bfloat16* __restrict__ yh,      // SPLIT_OUT
                 __nv_bfloat16* __restrict__ yl,      // SPLIT_OUT
                 float* __restrict__ yo)              // !SPLIT_OUT
{
    extern __shared__ __nv_bfloat16 sbuf[];     // 4 x (hi+lo) K buffers

    const int tid  = threadIdx.x;
    const int w    = tid >> 5;
    const int lane = tid & 31;
    const int h    = blockIdx.y & (H - 1);
    const int b    = blockIdx.y >> 4;
    const int i_base = blockIdx.x * TI;

    const size_t slice = (size_t)b * L * D + h * DK;
    const __nv_bfloat16* xhb = xh + slice;
    const __nv_bfloat16* xlb = xl + slice;

    float t6[6];
#pragma unroll
    for (int q = 0; q < 6; ++q) t6[q] = tanhf(w6[h * 6 + q]);

    // lane-derived ldmatrix offset pieces
    const int lrA = (lane & 7) + ((lane >> 3) & 1) * 8;  // A / trans-B row part
    const int lcA = ((lane >> 4) & 1) * 8;               // A / trans-B col part
    const int lrK = (lane & 7) + ((lane >> 4) & 1) * 8;  // non-trans B row part
    const int lcK = ((lane >> 3) & 1) * 8;               // non-trans B col part

    // prologue: Q -> buf3, K0 -> buf0, K1 -> buf1 (separate groups)
    stage_async(xhb, xlb, i_base, sbuf + 3 * BUFE, tid); cp_commit();
    stage_async(xhb, xlb, 0,      sbuf + 0 * BUFE, tid); cp_commit();
    stage_async(xhb, xlb, TJ,     sbuf + 1 * BUFE, tid); cp_commit();
    cp_wait<1>();            // Q and K0 landed
    __syncthreads();

    // hoist Q A-fragments (unscaled; 1/8 folded into exp argument)
    uint32_t qh[4][4], ql[4][4];
#pragma unroll
    for (int kc = 0; kc < 4; ++kc) {
        const int off = (w * 16 + lrA) * LDS + kc * 16 + lcA;
        ldmx4(smem_u32(sbuf + 3 * BUFE + off),        qh[kc][0], qh[kc][1], qh[kc][2], qh[kc][3]);
        ldmx4(smem_u32(sbuf + 3 * BUFE + TILE + off), ql[kc][0], ql[kc][1], ql[kc][2], ql[kc][3]);
    }

    float o[8][4];
#pragma unroll
    for (int nt = 0; nt < 8; ++nt)
#pragma unroll
        for (int v = 0; v < 4; ++v) o[nt][v] = 0.f;
    float l0 = 0.f, l1 = 0.f;

    const int gi0 = i_base + w * 16 + (lane >> 2);
    const int gi1 = gi0 + 8;
    const int jlo0 = (gi0 / KCLS) * KCLS;
    const int jlo1 = (gi1 / KCLS) * KCLS;
    // per-row weight quadruple {in_class, out_class, diag, query_col};
    // query row (gi==NKQ): everything t6[4] except col NKQ -> t6[5]
    float wr0[4], wr1[4];
    if (gi0 == NKQ) { wr0[0] = wr0[1] = t6[4]; wr0[2] = wr0[3] = t6[5]; }
    else            { wr0[0] = t6[1]; wr0[1] = t6[2]; wr0[2] = t6[0]; wr0[3] = t6[3]; }
    if (gi1 == NKQ) { wr1[0] = wr1[1] = t6[4]; wr1[2] = wr1[3] = t6[5]; }
    else            { wr1[0] = t6[1]; wr1[1] = t6[2]; wr1[2] = t6[0]; wr1[3] = t6[3]; }

    // S(0) into acc (tensor pipe fills while we enter the loop)
    float acc[8][4];
    s_phase(sbuf, qh, ql, acc, lrK, lcK);

    // Pipelined mainloop: softmax(jt) -> [wait K(jt+1)] -> S(jt+1) -> PV(jt).
    // Buffer reuse distance >= 2 iterations => single __syncthreads per tile.
    for (int jt = 0; jt < NT; ++jt) {
        if (jt + 2 < NT)
            stage_async(xhb, xlb, (jt + 2) * TJ, sbuf + ((jt + 2) & 3) * BUFE, tid);
        cp_commit();         // always commit (possibly empty) to keep wait bookkeeping exact

        uint32_t ah[4][4], al[4][4];
        if (jt == NT - 1)
            softmax_pack<true >(acc, jt * TJ, gi0, gi1, jlo0, jlo1, wr0, wr1, ah, al, l0, l1, lane);
        else
            softmax_pack<false>(acc, jt * TJ, gi0, gi1, jlo0, jlo1, wr0, wr1, ah, al, l0, l1, lane);

        cp_wait<1>();        // K(jt+1) landed
        __syncthreads();     // visibility + buffer-reuse safety (skew <= 1 iter)

        if (jt + 1 < NT)
            s_phase(sbuf + ((jt + 1) & 3) * BUFE, qh, ql, acc, lrK, lcK);
        pv_phase(sbuf + (jt & 3) * BUFE, ah, al, o, lrA, lcA);
    }

    // ---- epilogue: reduce denominators once, divide, write ----
    l0 += __shfl_xor_sync(0xffffffffu, l0, 1);
    l0 += __shfl_xor_sync(0xffffffffu, l0, 2);
    l1 += __shfl_xor_sync(0xffffffffu, l1, 1);
    l1 += __shfl_xor_sync(0xffffffffu, l1, 2);
    const float inv0 = 1.f / l0, inv1 = 1.f / l1;

#pragma unroll
    for (int nt = 0; nt < 8; ++nt) {
        const int c = nt * 8 + (lane & 3) * 2;
        if (SPLIT_OUT) {
            if (gi0 < L) {
                uint32_t hi, lo;
                split2(o[nt][0] * inv0, o[nt][1] * inv0, hi, lo);
                *reinterpret_cast<uint32_t*>(yh + slice + (size_t)gi0 * D + c) = hi;
                *reinterpret_cast<uint32_t*>(yl + slice + (size_t)gi0 * D + c) = lo;
            }
            if (gi1 < L) {
                uint32_t hi, lo;
                split2(o[nt][2] * inv1, o[nt][3] * inv1, hi, lo);
                *reinterpret_cast<uint32_t*>(yh + slice + (size_t)gi1 * D + c) = hi;
                *reinterpret_cast<uint32_t*>(yl + slice + (size_t)gi1 * D + c) = lo;
            }
        } else {
            if (gi0 < L)
                *reinterpret_cast<float2*>(yo + slice + (size_t)gi0 * D + c) =
                    make_float2(o[nt][0] * inv0, o[nt][1] * inv0);
            if (gi1 < L)
                *reinterpret_cast<float2*>(yo + slice + (size_t)gi1 * D + c) =
                    make_float2(o[nt][2] * inv1, o[nt][3] * inv1);
        }
    }
}

extern "C" void kernel_launch(void* const* d_in, const int* in_sizes, int n_in,
                              void* d_out, int out_size)
{
    const float* samples = (const float*)d_in[0];   // [B, L, D] fp32
    const float* weights = (const float*)d_in[1];   // [2, H, 6] fp32
    float* out = (float*)d_out;                     // [B, L, D] fp32

    __nv_bfloat16 *xh, *xl, *yh, *yl;
    cudaGetSymbolAddress((void**)&xh, g_xh);
    cudaGetSymbolAddress((void**)&xl, g_xl);
    cudaGetSymbolAddress((void**)&yh, g_yh);
    cudaGetSymbolAddress((void**)&yl, g_yl);

    cudaFuncSetAttribute(encoder_layer_tc<true >,
                         cudaFuncAttributeMaxDynamicSharedMemorySize, SMEM_BYTES);
    cudaFuncSetAttribute(encoder_layer_tc<false>,
                         cudaFuncAttributeMaxDynamicSharedMemorySize, SMEM_BYTES);

    const int total4 = B * L * D / 4;               // exactly divisible
    convert_split<<<total4 / 256, 256>>>(samples, xh, xl);

    dim3 grid(NT, B * H);                           // 16 x 128
    encoder_layer_tc<true ><<<grid, 128, SMEM_BYTES>>>(xh, xl, weights,          yh, yl, nullptr);
    encoder_layer_tc<false><<<grid, 128, SMEM_BYTES>>>(yh, yl, weights + H * 6, nullptr, nullptr, out);
}

// round 11
// speedup vs baseline: 1.0077x; 1.0077x over previous
#include <cuda_runtime.h>
#include <cuda_bf16.h>
#include <cmath>
#include <cstdint>

// Problem constants (fixed by setup_inputs: B=8, L=20*50+1, d_model=1024, H=16, 2 layers)
namespace {
constexpr int B    = 8;
constexpr int L    = 1001;
constexpr int D    = 1024;
constexpr int H    = 16;
constexpr int DK   = 64;
constexpr int NKQ  = 1000;   // query row index
constexpr int KCLS = 50;     // class block size
constexpr int TI   = 64;     // row tile (4 warps x 16)
constexpr int TJ   = 64;     // key tile
constexpr int NT   = (L + TJ - 1) / TJ;   // 16
constexpr int LDS  = 72;     // bf16 elems per smem row (144B stride: conflict-free ldmatrix)
constexpr int TILE = TJ * LDS;            // elems per hi (or lo) tile
constexpr int BUFE = 2 * TILE;            // elems per buffer (hi+lo)
constexpr int SMEM_BYTES = 3 * BUFE * 2;  // 2 K bufs + 1 Q buf = 55296 B (4 CTAs/SM)
// fixed-base softmax: e^(s/8 - 24) = 2^(acc*C1 + C0). Scores are bounded (|s|<~16,
// diag >= 0 so denominator never vanishes); the common e^-24 scale cancels in o/l.
constexpr float C1 = 0.125f * 1.4426950408889634f;
constexpr float C0 = -24.0f * 1.4426950408889634f;
}

// bf16 hi/lo split activations (global scratch; no-alloc rule).
__device__ __nv_bfloat16 g_xh[(size_t)B * L * D];
__device__ __nv_bfloat16 g_xl[(size_t)B * L * D];
__device__ __nv_bfloat16 g_yh[(size_t)B * L * D];
__device__ __nv_bfloat16 g_yl[(size_t)B * L * D];

__device__ __forceinline__ uint32_t smem_u32(const void* p) {
    return (uint32_t)__cvta_generic_to_shared(p);
}
__device__ __forceinline__ void ldmx4(uint32_t a, uint32_t& r0, uint32_t& r1, uint32_t& r2, uint32_t& r3) {
    asm volatile("ldmatrix.sync.aligned.m8n8.x4.shared.b16 {%0,%1,%2,%3},[%4];"
                 : "=r"(r0), "=r"(r1), "=r"(r2), "=r"(r3) : "r"(a));
}
__device__ __forceinline__ void ldmx4t(uint32_t a, uint32_t& r0, uint32_t& r1, uint32_t& r2, uint32_t& r3) {
    asm volatile("ldmatrix.sync.aligned.m8n8.x4.trans.shared.b16 {%0,%1,%2,%3},[%4];"
                 : "=r"(r0), "=r"(r1), "=r"(r2), "=r"(r3) : "r"(a));
}
__device__ __forceinline__ void mma_bf16(float* d, const uint32_t* a, uint32_t b0, uint32_t b1) {
    asm volatile("mma.sync.aligned.m16n8k16.row.col.f32.bf16.bf16.f32 "
                 "{%0,%1,%2,%3},{%4,%5,%6,%7},{%8,%9},{%0,%1,%2,%3};"
                 : "+f"(d[0]), "+f"(d[1]), "+f"(d[2]), "+f"(d[3])
                 : "r"(a[0]), "r"(a[1]), "r"(a[2]), "r"(a[3]), "r"(b0), "r"(b1));
}
__device__ __forceinline__ float ex2(float x) {
    float r; asm("ex2.approx.ftz.f32 %0,%1;" : "=f"(r) : "f"(x)); return r;
}
// Fast 2-term bf16 split of pair (a,b): a -> low halves, b -> high halves.
__device__ __forceinline__ void split2(float a, float b, uint32_t& hi, uint32_t& lo) {
    uint32_t h;
    asm("cvt.rn.bf16x2.f32 %0, %1, %2;" : "=r"(h) : "f"(b), "f"(a));
    const float fa = __uint_as_float(h << 16);
    const float fb = __uint_as_float(h & 0xffff0000u);
    uint32_t l;
    asm("cvt.rn.bf16x2.f32 %0, %1, %2;" : "=r"(l) : "f"(b - fb), "f"(a - fa));
    hi = h; lo = l;
}
__device__ __forceinline__ void cp_commit() { asm volatile("cp.async.commit_group;"); }
template<int N> __device__ __forceinline__ void cp_wait() {
    asm volatile("cp.async.wait_group %0;" :: "n"(N));
}

// Async-stage a 64-row tile (this head's 64 bf16 cols) of hi+lo into smem buffer.
// 1024 16B chunks / 128 threads = 8 per thread. OOB rows zero-filled via src-size=0.
__device__ __forceinline__ void stage_async(const __nv_bfloat16* __restrict__ gh,
                                            const __nv_bfloat16* __restrict__ gl,
                                            int base_row, __nv_bfloat16* sbuf, int tid) {
#pragma unroll
    for (int it = 0; it < 8; ++it) {
        int idx = tid + 128 * it;          // 0..1023
        int arr = idx >> 9;                // 0 = hi, 1 = lo
        int rem = idx & 511;
        int row = rem >> 3;
        int ch  = rem & 7;                 // 16B chunk within 128B row segment
        int g   = base_row + row;
        const __nv_bfloat16* src = (arr ? gl : gh) + (size_t)g * D + ch * 8;
        uint32_t dst = smem_u32(sbuf + arr * TILE + row * LDS + ch * 8);
        int sz = (g < L) ? 16 : 0;
        asm volatile("cp.async.ca.shared.global [%0], [%1], 16, %2;"
                     :: "r"(dst), "l"(src), "r"(sz));
    }
}

// ---- S = Q K^T (bf16x3, unscaled). Q fragments reloaded per k-chunk from the
// resident Q smem buffer (8 transient regs instead of 32 hoisted). ----
__device__ __forceinline__ void s_phase(const __nv_bfloat16* kb, const __nv_bfloat16* qb,
                                        int qoff, float (&acc)[8][4], int lrK, int lcK) {
#pragma unroll
    for (int nt = 0; nt < 8; ++nt)
#pragma unroll
        for (int v = 0; v < 4; ++v) acc[nt][v] = 0.f;
#pragma unroll
    for (int kc = 0; kc < 4; ++kc) {
        uint32_t qh[4], ql[4];
        ldmx4(smem_u32(qb + qoff + kc * 16),        qh[0], qh[1], qh[2], qh[3]);
        ldmx4(smem_u32(qb + TILE + qoff + kc * 16), ql[0], ql[1], ql[2], ql[3]);
#pragma unroll
        for (int ntp = 0; ntp < 4; ++ntp) {
            const int off = (16 * ntp + lrK) * LDS + kc * 16 + lcK;
            uint32_t bh0, bh1, bh2, bh3, bl0, bl1, bl2, bl3;
            ldmx4(smem_u32(kb + off),        bh0, bh1, bh2, bh3);
            ldmx4(smem_u32(kb + TILE + off), bl0, bl1, bl2, bl3);
            mma_bf16(acc[2 * ntp],     qh, bh0, bh1);
            mma_bf16(acc[2 * ntp],     qh, bl0, bl1);
            mma_bf16(acc[2 * ntp],     ql, bh0, bh1);
            mma_bf16(acc[2 * ntp + 1], qh, bh2, bh3);
            mma_bf16(acc[2 * ntp + 1], qh, bl2, bl3);
            mma_bf16(acc[2 * ntp + 1], ql, bh2, bh3);
        }
    }
}

// ---- O += P V (V tile == K tile data, trans ldmatrix) ----
__device__ __forceinline__ void pv_phase(const __nv_bfloat16* kb,
                                         const uint32_t (&ah)[4][4], const uint32_t (&al)[4][4],
                                         float (&o)[8][4], int lrA, int lcA) {
#pragma unroll
    for (int kc = 0; kc < 4; ++kc) {
#pragma unroll
        for (int ntp = 0; ntp < 4; ++ntp) {
            const int off = (kc * 16 + lrA) * LDS + 16 * ntp + lcA;
            uint32_t vh0, vh1, vh2, vh3, vl0, vl1, vl2, vl3;
            ldmx4t(smem_u32(kb + off),        vh0, vh1, vh2, vh3);
            ldmx4t(smem_u32(kb + TILE + off), vl0, vl1, vl2, vl3);
            mma_bf16(o[2 * ntp],     ah[kc], vh0, vh1);
            mma_bf16(o[2 * ntp],     ah[kc], vl0, vl1);
            mma_bf16(o[2 * ntp],     al[kc], vh0, vh1);
            mma_bf16(o[2 * ntp + 1], ah[kc], vh2, vh3);
            mma_bf16(o[2 * ntp + 1], ah[kc], vl2, vl3);
            mma_bf16(o[2 * ntp + 1], al[kc], vh2, vh3);
        }
    }
}

// Softmax + structured multiplier + pack P into A-fragments.
// wr* = {w_in_class, w_out_class, w_diag, w_querycol} per owned row.
template<bool MASK>
__device__ __forceinline__ void softmax_pack(const float (&acc)[8][4], int j_base,
                                             int gi0, int gi1, int jlo0, int jlo1,
                                             const float* wr0, const float* wr1,
                                             uint32_t (&ah)[4][4], uint32_t (&al)[4][4],
                                             float& l0, float& l1, int lane)
{
#pragma unroll
    for (int nt = 0; nt < 8; ++nt) {
        const int gj0 = j_base + nt * 8 + (lane & 3) * 2;
        const int gj1 = gj0 + 1;
        float e00 = ex2(fmaf(acc[nt][0], C1, C0));
        float e01 = ex2(fmaf(acc[nt][1], C1, C0));
        float e10 = ex2(fmaf(acc[nt][2], C1, C0));
        float e11 = ex2(fmaf(acc[nt][3], C1, C0));
        if (MASK) {
            if (gj0 >= L) { e00 = 0.f; e10 = 0.f; }
            if (gj1 >= L) { e01 = 0.f; e11 = 0.f; }
        }
        l0 += e00 + e01;
        l1 += e10 + e11;
        float t00 = ((unsigned)(gj0 - jlo0) < (unsigned)KCLS) ? wr0[0] : wr0[1];
        float t01 = ((unsigned)(gj1 - jlo0) < (unsigned)KCLS) ? wr0[0] : wr0[1];
        float t10 = ((unsigned)(gj0 - jlo1) < (unsigned)KCLS) ? wr1[0] : wr1[1];
        float t11 = ((unsigned)(gj1 - jlo1) < (unsigned)KCLS) ? wr1[0] : wr1[1];
        if (gj0 == gi0) t00 = wr0[2];
        if (gj1 == gi0) t01 = wr0[2];
        if (gj0 == gi1) t10 = wr1[2];
        if (gj1 == gi1) t11 = wr1[2];
        if (gj0 == NKQ) { t00 = wr0[3]; t10 = wr1[3]; }
        if (gj1 == NKQ) { t01 = wr0[3]; t11 = wr1[3]; }
        const int kc = nt >> 1, of = (nt & 1) * 2;
        split2(e00 * t00, e01 * t01, ah[kc][of],     al[kc][of]);
        split2(e10 * t10, e11 * t11, ah[kc][of + 1], al[kc][of + 1]);
    }
}

// Initial fp32 -> bf16 hi/lo split (one-time).
__global__ void convert_split(const float* __restrict__ x,
                              __nv_bfloat16* __restrict__ xh,
                              __nv_bfloat16* __restrict__ xl) {
    size_t i = ((size_t)blockIdx.x * blockDim.x + threadIdx.x) * 4;
    float4 v = *reinterpret_cast<const float4*>(x + i);
    uint32_t h0, l0, h1, l1;
    split2(v.x, v.y, h0, l0);
    split2(v.z, v.w, h1, l1);
    *reinterpret_cast<uint2*>(xh + i) = make_uint2(h0, h1);
    *reinterpret_cast<uint2*>(xl + i) = make_uint2(l0, l1);
}

template<bool SPLIT_OUT>
__global__ void __launch_bounds__(128, 4)
encoder_layer_tc(const __nv_bfloat16* __restrict__ xh,
                 const __nv_bfloat16* __restrict__ xl,
                 const float* __restrict__ w6,        // [H][6] for this layer
                 __nv_bfloat16* __restrict__ yh,      // SPLIT_OUT
                 __nv_bfloat16* __restrict__ yl,      // SPLIT_OUT
                 float* __restrict__ yo)              // !SPLIT_OUT
{
    extern __shared__ __nv_bfloat16 sbuf[];     // [K0][K1][Q] hi+lo buffers

    const int tid  = threadIdx.x;
    const int w    = tid >> 5;
    const int lane = tid & 31;
    const int h    = blockIdx.y & (H - 1);
    const int b    = blockIdx.y >> 4;
    const int i_base = blockIdx.x * TI;

    const size_t slice = (size_t)b * L * D + h * DK;
    const __nv_bfloat16* xhb = xh + slice;
    const __nv_bfloat16* xlb = xl + slice;
    __nv_bfloat16* qb = sbuf + 2 * BUFE;        // resident Q buffer

    float t6[6];
#pragma unroll
    for (int q = 0; q < 6; ++q) t6[q] = tanhf(w6[h * 6 + q]);

    // lane-derived ldmatrix offset pieces
    const int lrA = (lane & 7) + ((lane >> 3) & 1) * 8;  // A / trans-B row part
    const int lcA = ((lane >> 4) & 1) * 8;               // A / trans-B col part
    const int lrK = (lane & 7) + ((lane >> 4) & 1) * 8;  // non-trans B row part
    const int lcK = ((lane >> 3) & 1) * 8;               // non-trans B col part
    const int qoff = (w * 16 + lrA) * LDS + lcA;         // per-tile Q fragment base

    // prologue: Q -> qb, K0 -> buf0, K1 -> buf1 (separate groups)
    stage_async(xhb, xlb, i_base, qb,              tid); cp_commit();
    stage_async(xhb, xlb, 0,      sbuf,            tid); cp_commit();
    stage_async(xhb, xlb, TJ,     sbuf + BUFE,     tid); cp_commit();

    float o[8][4];
#pragma unroll
    for (int nt = 0; nt < 8; ++nt)
#pragma unroll
        for (int v = 0; v < 4; ++v) o[nt][v] = 0.f;
    float l0 = 0.f, l1 = 0.f;

    const int gi0 = i_base + w * 16 + (lane >> 2);
    const int gi1 = gi0 + 8;
    const int jlo0 = (gi0 / KCLS) * KCLS;
    const int jlo1 = (gi1 / KCLS) * KCLS;
    // per-row weight quadruple {in_class, out_class, diag, query_col};
    // query row (gi==NKQ): everything t6[4] except col NKQ -> t6[5]
    float wr0[4], wr1[4];
    if (gi0 == NKQ) { wr0[0] = wr0[1] = t6[4]; wr0[2] = wr0[3] = t6[5]; }
    else            { wr0[0] = t6[1]; wr0[1] = t6[2]; wr0[2] = t6[0]; wr0[3] = t6[3]; }
    if (gi1 == NKQ) { wr1[0] = wr1[1] = t6[4]; wr1[2] = wr1[3] = t6[5]; }
    else            { wr1[0] = t6[1]; wr1[1] = t6[2]; wr1[2] = t6[0]; wr1[3] = t6[3]; }

    for (int jt = 0; jt < NT; ++jt) {
        const __nv_bfloat16* kb = sbuf + (jt & 1) * BUFE;   // K(jt)

        cp_wait<1>();        // Q, K0..K(jt) landed; K(jt+1) may be in flight
        __syncthreads();

        float acc[8][4];
        s_phase(kb, qb, qoff, acc, lrK, lcK);

        uint32_t ah[4][4], al[4][4];
        if (jt == NT - 1)
            softmax_pack<true >(acc, jt * TJ, gi0, gi1, jlo0, jlo1, wr0, wr1, ah, al, l0, l1, lane);
        else
            softmax_pack<false>(acc, jt * TJ, gi0, gi1, jlo0, jlo1, wr0, wr1, ah, al, l0, l1, lane);

        pv_phase(kb, ah, al, o, lrA, lcA);

        __syncthreads();     // all warps done reading kb before restaging it
        if (jt + 2 < NT)
            stage_async(xhb, xlb, (jt + 2) * TJ, sbuf + (jt & 1) * BUFE, tid);
        cp_commit();         // always commit (possibly empty) to keep wait bookkeeping exact
    }

    // ---- epilogue: reduce denominators once, divide, write ----
    l0 += __shfl_xor_sync(0xffffffffu, l0, 1);
    l0 += __shfl_xor_sync(0xffffffffu, l0, 2);
    l1 += __shfl_xor_sync(0xffffffffu, l1, 1);
    l1 += __shfl_xor_sync(0xffffffffu, l1, 2);
    const float inv0 = 1.f / l0, inv1 = 1.f / l1;

#pragma unroll
    for (int nt = 0; nt < 8; ++nt) {
        const int c = nt * 8 + (lane & 3) * 2;
        if (SPLIT_OUT) {
            if (gi0 < L) {
                uint32_t hi, lo;
                split2(o[nt][0] * inv0, o[nt][1] * inv0, hi, lo);
                *reinterpret_cast<uint32_t*>(yh + slice + (size_t)gi0 * D + c) = hi;
                *reinterpret_cast<uint32_t*>(yl + slice + (size_t)gi0 * D + c) = lo;
            }
            if (gi1 < L) {
                uint32_t hi, lo;
                split2(o[nt][2] * inv1, o[nt][3] * inv1, hi, lo);
                *reinterpret_cast<uint32_t*>(yh + slice + (size_t)gi1 * D + c) = hi;
                *reinterpret_cast<uint32_t*>(yl + slice + (size_t)gi1 * D + c) = lo;
            }
        } else {
            if (gi0 < L)
                *reinterpret_cast<float2*>(yo + slice + (size_t)gi0 * D + c) =
                    make_float2(o[nt][0] * inv0, o[nt][1] * inv0);
            if (gi1 < L)
                *reinterpret_cast<float2*>(yo + slice + (size_t)gi1 * D + c) =
                    make_float2(o[nt][2] * inv1, o[nt][3] * inv1);
        }
    }
}

extern "C" void kernel_launch(void* const* d_in, const int* in_sizes, int n_in,
                              void* d_out, int out_size)
{
    const float* samples = (const float*)d_in[0];   // [B, L, D] fp32
    const float* weights = (const float*)d_in[1];   // [2, H, 6] fp32
    float* out = (float*)d_out;                     // [B, L, D] fp32

    __nv_bfloat16 *xh, *xl, *yh, *yl;
    cudaGetSymbolAddress((void**)&xh, g_xh);
    cudaGetSymbolAddress((void**)&xl, g_xl);
    cudaGetSymbolAddress((void**)&yh, g_yh);
    cudaGetSymbolAddress((void**)&yl, g_yl);

    cudaFuncSetAttribute(encoder_layer_tc<true >,
                         cudaFuncAttributeMaxDynamicSharedMemorySize, SMEM_BYTES);
    cudaFuncSetAttribute(encoder_layer_tc<false>,
                         cudaFuncAttributeMaxDynamicSharedMemorySize, SMEM_BYTES);

    const int total4 = B * L * D / 4;               // exactly divisible
    convert_split<<<total4 / 256, 256>>>(samples, xh, xl);

    dim3 grid(NT, B * H);                           // 16 x 128
    encoder_layer_tc<true ><<<grid, 128, SMEM_BYTES>>>(xh, xl, weights,          yh, yl, nullptr);
    encoder_layer_tc<false><<<grid, 128, SMEM_BYTES>>>(yh, yl, weights + H * 6, nullptr, nullptr, out);
}